// round 15
// baseline (speedup 1.0000x reference)
#include <cuda_runtime.h>
#include <cuda_fp16.h>
#include <math.h>
#include <stdint.h>

#define BB 8
#define NN 4096
#define KKN 20
#define BN_TOTAL (BB*NN)          // 32768
#define R_EDGE (BB*NN*KKN)        // 655360
#define EPSI 1e-5f

// ---------------- scratch (device globals; no allocation allowed) ------------
__device__ float    g_h[(size_t)BN_TOTAL*128];
__device__ float    g_x1[BN_TOTAL*64];
__device__ float    g_P1[BN_TOTAL*64],  g_Q1[BN_TOTAL*64];
__device__ float    g_P2[BN_TOTAL*128], g_Q2[BN_TOTAL*128];
__device__ uint32_t g_x1mx[BN_TOTAL*64],  g_x1mn[BN_TOTAL*64];
__device__ uint32_t g_x2mx[BN_TOTAL*128], g_x2mn[BN_TOTAL*128];
__device__ int      g_idx[R_EDGE];
__device__ double   g_sum[5][128];
__device__ double   g_ssq[5][128];
__device__ uint32_t g_wimg[61440];
__device__ float    g_zero[128];

#define OFF_C1L2 0
#define OFF_P2   4096
#define OFF_Q2   12288
#define OFF_C2L2 20480
#define OFF_CLS  36864

// ---------------- helpers -----------------------------------------------------
__device__ __forceinline__ uint32_t hpack(float v0, float v1, float& r0, float& r1) {
    __half h0 = __float2half_rn(v0), h1 = __float2half_rn(v1);
    r0 = v0 - __half2float(h0);
    r1 = v1 - __half2float(h1);
    __half2 p = __halves2half2(h0, h1);
    return *(uint32_t*)&p;
}
__device__ __forceinline__ uint32_t hpack2(float v0, float v1) {
    __half2 p = __halves2half2(__float2half_rn(v0), __float2half_rn(v1));
    return *(uint32_t*)&p;
}
__device__ __forceinline__ void mma16(float* c, const uint32_t* a, const uint32_t* b) {
    asm volatile("mma.sync.aligned.m16n8k16.row.col.f32.f16.f16.f32 "
        "{%0,%1,%2,%3}, {%4,%5,%6,%7}, {%8,%9}, {%0,%1,%2,%3};"
        : "+f"(c[0]), "+f"(c[1]), "+f"(c[2]), "+f"(c[3])
        : "r"(a[0]), "r"(a[1]), "r"(a[2]), "r"(a[3]), "r"(b[0]), "r"(b[1]));
}
__device__ __forceinline__ void affine_init(int stage, const float* gam, const float* bet,
                                            float n, int cout, float* sSc, float* sSh, int tid) {
    if (tid < cout) {
        double mean = g_sum[stage][tid] / (double)n;
        double var  = g_ssq[stage][tid] / (double)n - mean*mean;
        float  s    = gam[tid] / sqrtf((float)var + EPSI);
        sSc[tid] = s;
        sSh[tid] = bet[tid] - (float)mean * s;
    }
}
__device__ __forceinline__ uint32_t fkey(float f) {
    uint32_t u = __float_as_uint(f);
    return u ^ ((u >> 31) ? 0xffffffffu : 0x80000000u);
}
__device__ __forceinline__ float funkey(uint32_t u) {
    return __uint_as_float(u ^ ((u >> 31) ? 0x80000000u : 0xffffffffu));
}

// ---------------- front: knn4 (blocks 0..127) + prep (blocks 128..14567) ------
__global__ void __launch_bounds__(256)
front_kernel(const float* __restrict__ X, int* __restrict__ out_idx,
             const float* __restrict__ c1w1, const float* __restrict__ c1b1,
             const float* __restrict__ c1w2, const float* __restrict__ c2w1,
             const float* __restrict__ c2w2, const float* __restrict__ clsw1,
             uint32_t* __restrict__ wimg) {
    int tid = threadIdx.x;
    if (blockIdx.x < 128) {
        // ------- knn4: 256 points per block, TJ=256, 1 thread/point ----------
        constexpr int TJ = 256;
        __shared__ float4 sxj[TJ];
        __shared__ float  sx2[TJ];
        const float4* X4 = (const float4*)X;

        if (blockIdx.x == 0) {
            for (int t = tid; t < 640; t += 256) {
                (&g_sum[0][0])[t] = 0.0; (&g_ssq[0][0])[t] = 0.0;
            }
        }
        int b = blockIdx.x >> 4;                   // 16 blocks per batch
        int i = (blockIdx.x & 15) * 256 + tid;

        float4 xi = X4[(size_t)b*NN + i];
        float x2i = xi.x*xi.x + xi.y*xi.y + xi.z*xi.z + xi.w*xi.w;

        float td[KKN]; int ti[KKN];
#pragma unroll
        for (int s = 0; s < KKN; s++) { td[s] = 3.4e38f; ti[s] = 0; }

        for (int j0 = 0; j0 < NN; j0 += TJ) {
            __syncthreads();
            {
                float4 v = X4[(size_t)b*NN + j0 + tid];
                sxj[tid] = v;
                sx2[tid] = v.x*v.x + v.y*v.y + v.z*v.z + v.w*v.w;
            }
            __syncthreads();
            for (int jj = 0; jj < TJ; jj++) {
                float4 v = sxj[jj];
                float dot = xi.x*v.x + xi.y*v.y + xi.z*v.z + xi.w*v.w;
                float d = x2i + sx2[jj] - 2.0f*dot;
                if (d < td[KKN-1]) {
                    td[KKN-1] = d; ti[KKN-1] = j0 + jj;
#pragma unroll
                    for (int s = KKN-1; s > 0; s--) {
                        if (td[s] < td[s-1]) {
                            float t0 = td[s]; td[s] = td[s-1]; td[s-1] = t0;
                            int   u0 = ti[s]; ti[s] = ti[s-1]; ti[s-1] = u0;
                        }
                    }
                }
            }
        }
#pragma unroll
        for (int s = 0; s < KKN; s++) out_idx[(size_t)(b*NN + i)*KKN + s] = ti[s];
        return;
    }
    // ------- prep: pq1 + weight prep + max/min buffer init -------------------
    __shared__ float sWd[4*64], sWb[4*64], sB[64];
    int bid = blockIdx.x - 128;
    if (bid < 8192) {
        {
            int ci = tid >> 6, c = tid & 63;
            sWd[ci*64+c] = c1w1[ci*64+c] - c1w1[(ci+4)*64+c];
            sWb[ci*64+c] = c1w1[(ci+4)*64+c];
        }
        if (tid < 64) sB[tid] = c1b1[tid];
        __syncthreads();
        int c = tid & 63;
        int bn = bid*4 + (tid >> 6);
        float4 x = ((const float4*)X)[bn];
        float p = sB[c] + x.x*sWd[c] + x.y*sWd[64+c] + x.z*sWd[128+c] + x.w*sWd[192+c];
        float q =         x.x*sWb[c] + x.y*sWb[64+c] + x.z*sWb[128+c] + x.w*sWb[192+c];
        g_P1[(size_t)bn*64 + c] = p;
        g_Q1[(size_t)bn*64 + c] = q;
    } else if (bid < 8296) {
        int wb = bid - 8192;
        if (wb < 8) {
            int t = wb*256 + tid;
            if (t < 32*64) {
                int k2 = t / 64, n = t % 64;
                float w0 = c1w2[(size_t)(2*k2)*64 + n], w1 = c1w2[(size_t)(2*k2+1)*64 + n];
                float r0, r1;
                wimg[OFF_C1L2 + t] = hpack(w0, w1, r0, r1);
                wimg[OFF_C1L2 + 32*64 + t] = hpack2(r0, r1);
            }
        } else if (wb < 24) {
            int t = (wb-8)*256 + tid;
            if (t < 32*128) {
                int k2 = t / 128, n = t % 128;
                float wt0 = c2w1[(size_t)(2*k2)*128 + n],    wt1 = c2w1[(size_t)(2*k2+1)*128 + n];
                float wb0 = c2w1[(size_t)(2*k2+64)*128 + n], wb1 = c2w1[(size_t)(2*k2+65)*128 + n];
                float r0, r1;
                wimg[OFF_P2 + t] = hpack(wt0 - wb0, wt1 - wb1, r0, r1);
                wimg[OFF_P2 + 32*128 + t] = hpack2(r0, r1);
                wimg[OFF_Q2 + t] = hpack(wb0, wb1, r0, r1);
                wimg[OFF_Q2 + 32*128 + t] = hpack2(r0, r1);
            }
        } else if (wb < 56) {
            int t = (wb-24)*256 + tid;
            if (t < 64*128) {
                int k2 = t / 128, n = t % 128;
                float w0 = c2w2[(size_t)(2*k2)*128 + n], w1 = c2w2[(size_t)(2*k2+1)*128 + n];
                float r0, r1;
                wimg[OFF_C2L2 + t] = hpack(w0, w1, r0, r1);
                wimg[OFF_C2L2 + 64*128 + t] = hpack2(r0, r1);
            }
        } else {
            int t = (wb-56)*256 + tid;
            if (t < 96*128) {
                int k2 = t / 128, n = t % 128;
                float w0 = clsw1[(size_t)(2*k2)*128 + n], w1 = clsw1[(size_t)(2*k2+1)*128 + n];
                float r0, r1;
                wimg[OFF_CLS + t] = hpack(w0, w1, r0, r1);
                wimg[OFF_CLS + 96*128 + t] = hpack2(r0, r1);
            }
        }
    } else {
        int rel = bid - 8296;
        uint32_t* dst; uint32_t val;
        size_t off;
        if (rel < 1024)      { dst = g_x1mx; val = 0u;          off = (size_t)rel*2048; }
        else if (rel < 2048) { dst = g_x1mn; val = 0xffffffffu; off = (size_t)(rel-1024)*2048; }
        else if (rel < 4096) { dst = g_x2mx; val = 0u;          off = (size_t)(rel-2048)*2048; }
        else                 { dst = g_x2mn; val = 0xffffffffu; off = (size_t)(rel-4096)*2048; }
        uint4 v4 = make_uint4(val, val, val, val);
        uint4* d4 = (uint4*)(dst + off);
#pragma unroll
        for (int u = 0; u < 2; u++) d4[tid + 256*u] = v4;
    }
}

// ---------------- per-point layer-1 BN stats (float4, P loaded once) ----------
template<int COUT>
__global__ void __launch_bounds__(256)
stats1pt_kernel(const float* __restrict__ P, const float* __restrict__ Q,
                int sstage, int bn_base) {
    constexpr int CG  = COUT / 4;        // float4 channel groups
    constexpr int PPB = 256 / CG;        // points per block
    __shared__ int   sidx[PPB*KKN];
    __shared__ float sS[COUT], sQ2[COUT];
    int tid = threadIdx.x;
    int pt = tid / CG, cg = tid % CG;
    int bn0 = bn_base + blockIdx.x * PPB;
    for (int e = tid; e < PPB*KKN; e += 256)
        sidx[e] = g_idx[(size_t)(bn0 + e/KKN)*KKN + (e%KKN)];
    if (tid < COUT) { sS[tid] = 0.f; sQ2[tid] = 0.f; }
    __syncthreads();
    int bn = bn0 + pt;
    int b  = bn >> 12;
    float4 p = *(const float4*)&P[(size_t)bn*COUT + cg*4];
    float4 s = make_float4(0.f,0.f,0.f,0.f), q = make_float4(0.f,0.f,0.f,0.f);
#pragma unroll
    for (int k = 0; k < KKN; k++) {
        int j = sidx[pt*KKN + k];
        float4 qq = *(const float4*)&Q[((size_t)(b<<12) + j)*COUT + cg*4];
        float h0 = p.x + qq.x, h1 = p.y + qq.y, h2 = p.z + qq.z, h3 = p.w + qq.w;
        s.x += h0; s.y += h1; s.z += h2; s.w += h3;
        q.x += h0*h0; q.y += h1*h1; q.z += h2*h2; q.w += h3*h3;
    }
    atomicAdd(&sS[cg*4],   s.x); atomicAdd(&sS[cg*4+1], s.y);
    atomicAdd(&sS[cg*4+2], s.z); atomicAdd(&sS[cg*4+3], s.w);
    atomicAdd(&sQ2[cg*4],   q.x); atomicAdd(&sQ2[cg*4+1], q.y);
    atomicAdd(&sQ2[cg*4+2], q.z); atomicAdd(&sQ2[cg*4+3], q.w);
    __syncthreads();
    if (tid < COUT) {
        atomicAdd(&g_sum[sstage][tid], (double)sS[tid]);
        atomicAdd(&g_ssq[sstage][tid], (double)sQ2[tid]);
    }
}

// ---------------- finalize x1: relu(bn(max/min)) ------------------------------
__global__ void finalize_x1_kernel(const float* __restrict__ gam,
                                   const float* __restrict__ bet) {
    __shared__ float sSc[64], sSh[64];
    affine_init(1, gam, bet, (float)R_EDGE, 64, sSc, sSh, threadIdx.x);
    __syncthreads();
    int t = blockIdx.x*256 + threadIdx.x;
    int c = t & 63;
    float s = sSc[c];
    uint32_t u = (s >= 0.f) ? g_x1mx[t] : g_x1mn[t];
    g_x1[t] = fmaxf(fmaf(funkey(u), s, sSh[c]), 0.f);
}

// ---------------- knn for C=64: 128-row CTAs, smem-only merge -----------------
__global__ void __launch_bounds__(256, 1)
knn64_kernel(int* __restrict__ out_idx) {
    extern __shared__ uint32_t smu[];
    constexpr int AS = 36, BS = 136;
    uint32_t* XiH = smu;                     // [128][36]
    uint32_t* XiL = smu + 128*AS;
    uint32_t* XjH = smu + 2*128*AS;          // [32][136]
    uint32_t* XjL = XjH + 32*BS;
    float* dist = (float*)(XjL + 32*BS);     // [128][133]
    float* x2i  = dist + 128*133;            // [128]
    float* x2j  = x2i + 128;                 // [128]

    int tid = threadIdx.x, wid = tid >> 5, lane = tid & 31;
    int gid = lane >> 2, tig = lane & 3;
    int b  = blockIdx.x >> 5;
    int i0 = (blockIdx.x & 31) * 128;
    int mbase = (wid >> 2) * 64;
    int nbase = (wid & 3) * 32;
    int rrow = tid & 127, hf = tid >> 7;

    {
        const float4* row = (const float4*)&g_x1[(size_t)(b*NN + i0 + rrow)*64];
#pragma unroll
        for (int qq = 0; qq < 8; qq++) {
            int q = hf*8 + qq;
            float4 v = row[q];
            float r0, r1;
            XiH[rrow*AS + 2*q]   = hpack(v.x, v.y, r0, r1);
            XiL[rrow*AS + 2*q]   = hpack2(r0, r1);
            XiH[rrow*AS + 2*q+1] = hpack(v.z, v.w, r0, r1);
            XiL[rrow*AS + 2*q+1] = hpack2(r0, r1);
        }
    }
    if (tid < 128) {
        const float4* row = (const float4*)&g_x1[(size_t)(b*NN + i0 + tid)*64];
        float s = 0.f;
#pragma unroll
        for (int q = 0; q < 16; q++) {
            float4 v = row[q];
            s += v.x*v.x + v.y*v.y + v.z*v.z + v.w*v.w;
        }
        x2i[tid] = s;
    }

    float td[KKN]; int ti[KKN];
#pragma unroll
    for (int s = 0; s < KKN; s++) { td[s] = 3.4e38f; ti[s] = 0; }

    for (int jt = 0; jt < 32; jt++) {
        __syncthreads();
        {
            const float4* row = (const float4*)&g_x1[(size_t)(b*NN + jt*128 + rrow)*64];
#pragma unroll
            for (int qq = 0; qq < 8; qq++) {
                int q = hf*8 + qq;
                float4 v = row[q];
                float r0, r1;
                XjH[(2*q)*BS + rrow]   = hpack(v.x, v.y, r0, r1);
                XjL[(2*q)*BS + rrow]   = hpack2(r0, r1);
                XjH[(2*q+1)*BS + rrow] = hpack(v.z, v.w, r0, r1);
                XjL[(2*q+1)*BS + rrow] = hpack2(r0, r1);
            }
        }
        if (tid < 128) {
            const float4* row = (const float4*)&g_x1[(size_t)(b*NN + jt*128 + tid)*64];
            float s = 0.f;
#pragma unroll
            for (int q = 0; q < 16; q++) {
                float4 v = row[q];
                s += v.x*v.x + v.y*v.y + v.z*v.z + v.w*v.w;
            }
            x2j[tid] = s;
        }
        __syncthreads();

        float acc[4][4][4];
#pragma unroll
        for (int mt = 0; mt < 4; mt++)
#pragma unroll
            for (int nt = 0; nt < 4; nt++)
#pragma unroll
                for (int u = 0; u < 4; u++) acc[mt][nt][u] = 0.f;

#pragma unroll
        for (int kk = 0; kk < 4; kk++) {
            int k2b = kk*8;
            uint32_t ah[4][4], al[4][4], bh[4][2], bl[4][2];
#pragma unroll
            for (int mt = 0; mt < 4; mt++) {
                int rb = mbase + mt*16 + gid;
                ah[mt][0] = XiH[rb*AS + k2b + tig];
                ah[mt][1] = XiH[(rb+8)*AS + k2b + tig];
                ah[mt][2] = XiH[rb*AS + k2b + tig + 4];
                ah[mt][3] = XiH[(rb+8)*AS + k2b + tig + 4];
                al[mt][0] = XiL[rb*AS + k2b + tig];
                al[mt][1] = XiL[(rb+8)*AS + k2b + tig];
                al[mt][2] = XiL[rb*AS + k2b + tig + 4];
                al[mt][3] = XiL[(rb+8)*AS + k2b + tig + 4];
            }
#pragma unroll
            for (int nt = 0; nt < 4; nt++) {
                int cb = nbase + nt*8 + gid;
                bh[nt][0] = XjH[(k2b + tig)*BS + cb];
                bh[nt][1] = XjH[(k2b + tig + 4)*BS + cb];
                bl[nt][0] = XjL[(k2b + tig)*BS + cb];
                bl[nt][1] = XjL[(k2b + tig + 4)*BS + cb];
            }
#pragma unroll
            for (int mt = 0; mt < 4; mt++)
#pragma unroll
                for (int nt = 0; nt < 4; nt++) {
                    mma16(acc[mt][nt], ah[mt], bh[nt]);
                    mma16(acc[mt][nt], ah[mt], bl[nt]);
                    mma16(acc[mt][nt], al[mt], bh[nt]);
                    mma16(acc[mt][nt], al[mt], bl[nt]);
                }
        }
#pragma unroll
        for (int mt = 0; mt < 4; mt++)
#pragma unroll
            for (int nt = 0; nt < 4; nt++) {
                int row = mbase + mt*16 + gid;
                int col = nbase + nt*8 + tig*2;
                dist[row*133 + col]         = acc[mt][nt][0];
                dist[row*133 + col + 1]     = acc[mt][nt][1];
                dist[(row+8)*133 + col]     = acc[mt][nt][2];
                dist[(row+8)*133 + col + 1] = acc[mt][nt][3];
            }
        __syncthreads();
        {
            float xi2 = x2i[rrow];
            const float* drow = &dist[rrow*133 + hf*64];
            const float* xj2 = x2j + hf*64;
            for (int jj = 0; jj < 64; jj++) {
                float d = xi2 + xj2[jj] - 2.0f*drow[jj];
                if (d < td[KKN-1]) {
                    td[KKN-1] = d; ti[KKN-1] = jt*128 + hf*64 + jj;
#pragma unroll
                    for (int s = KKN-1; s > 0; s--) {
                        if (td[s] < td[s-1]) {
                            float t0 = td[s]; td[s] = td[s-1]; td[s-1] = t0;
                            int   u0 = ti[s]; ti[s] = ti[s-1]; ti[s-1] = u0;
                        }
                    }
                }
            }
        }
    }
    __syncthreads();
    float* md = dist;                      // [128][2][20]
    int*   mi = (int*)(dist + 5120);       // [128][2][20]
    {
        int base = rrow*40 + hf*20;
#pragma unroll
        for (int s = 0; s < KKN; s++) { md[base + s] = td[s]; mi[base + s] = ti[s]; }
    }
    __syncthreads();
    if (hf == 0) {
        const float* L = &md[rrow*40];
        const int*   I = &mi[rrow*40];
        int a = 0, bb2 = 0;
        int* orow = &out_idx[(size_t)(b*NN + i0 + rrow)*KKN];
#pragma unroll
        for (int s = 0; s < KKN; s++) {
            float da = L[a], db = L[20 + bb2];
            int ja = I[a],  jb = I[20 + bb2];
            bool takeA = (da < db) || (da == db && ja < jb);
            orow[s] = takeA ? ja : jb;
            if (takeA) a++; else bb2++;
        }
    }
}

// ================= fp16-split warp-MMA GEMM + fused epilogue =================
template<int CIN, int COUT, int MODE>
__global__ void __launch_bounds__(256, ((COUT == 64) ? 3 : 2))
tgemm_kernel(int sstage, int pstage, const uint32_t* __restrict__ Wimg,
             const float* __restrict__ bias,
             const float* __restrict__ gam, const float* __restrict__ bet, float nstat,
             const float* __restrict__ Pin, const float* __restrict__ Qin,
             float* __restrict__ Hout,
             uint32_t* __restrict__ dmx, uint32_t* __restrict__ dmn,
             const uint32_t* __restrict__ Wimg2, const float* __restrict__ bias2,
             float* __restrict__ Hout2) {
    extern __shared__ uint32_t smu[];
    constexpr int NCH = CIN / 64;
    constexpr int AS  = 36;
    constexpr int BS  = COUT + 8;
    constexpr int MT  = (COUT == 128) ? 4 : 2;
    uint32_t* Ah = smu;
    uint32_t* Al = smu + 128*AS;
    uint32_t* Bh = smu + 2*128*AS;
    uint32_t* Bl = Bh + 32*BS;
    float* stg = (float*)smu;
    __shared__ float sSc[128], sSh[128];
    __shared__ float sS[128], sQ2[128];

    int tid = threadIdx.x, wid = tid >> 5, lane = tid & 31;
    int gid = lane >> 2, tig = lane & 3;

    const uint32_t* Wp = Wimg;
    const float* biasp = bias;
    float* dstp = Hout;
    int r0;
    if constexpr (MODE == 4) {
        int half = gridDim.x >> 1;
        bool sec = (int)blockIdx.x >= half;
        Wp = sec ? Wimg2 : Wimg;
        biasp = sec ? bias2 : bias;
        dstp = sec ? Hout2 : Hout;
        r0 = (sec ? blockIdx.x - half : blockIdx.x) * 128;
    } else {
        r0 = blockIdx.x * 128;
    }

    if (tid < COUT) { sS[tid] = 0.f; sQ2[tid] = 0.f; }
    if constexpr (MODE == 3 || MODE == 2) {
        affine_init(pstage, gam, bet, nstat, (MODE == 3) ? CIN : 128, sSc, sSh, tid);
        __syncthreads();
    }

    int mbase = (COUT == 128) ? (wid >> 2) * 64 : (wid >> 1) * 32;
    int nbase = (COUT == 128) ? (wid & 3) * 32  : (wid & 1) * 32;

    float acc[MT][4][4];
#pragma unroll
    for (int mt = 0; mt < MT; mt++)
#pragma unroll
        for (int nt = 0; nt < 4; nt++)
#pragma unroll
            for (int u = 0; u < 4; u++) acc[mt][nt][u] = 0.f;

    for (int c = 0; c < NCH; c++) {
        if (c) __syncthreads();
        // ---- A chunk (float4-vectorized) ----
        for (int e4 = tid; e4 < 128*16; e4 += 256) {
            int m = e4 >> 4, k4 = e4 & 15;
            int kc = c*64 + k4*4;
            int r = r0 + m;
            float4 v;
            if constexpr (MODE == 3) {
                unsigned bn = (unsigned)r / KKN;
                int b = bn >> 12;
                int j = g_idx[r];
                float4 p = *(const float4*)&Pin[(size_t)bn*CIN + kc];
                float4 q = *(const float4*)&Qin[((size_t)(b<<12) + j)*CIN + kc];
                v.x = fmaxf(fmaf(p.x + q.x, sSc[kc],   sSh[kc]),   0.f);
                v.y = fmaxf(fmaf(p.y + q.y, sSc[kc+1], sSh[kc+1]), 0.f);
                v.z = fmaxf(fmaf(p.z + q.z, sSc[kc+2], sSh[kc+2]), 0.f);
                v.w = fmaxf(fmaf(p.w + q.w, sSc[kc+3], sSh[kc+3]), 0.f);
            } else if constexpr (MODE == 4) {
                v = *(const float4*)&Pin[(size_t)r*CIN + kc];
            } else {
                if (kc < 64) {
                    v = *(const float4*)&Pin[(size_t)r*64 + kc];
                } else {
                    int cc = kc - 64;
                    const uint4 ux = *(const uint4*)&dmx[(size_t)r*128 + cc];
                    const uint4 un = *(const uint4*)&dmn[(size_t)r*128 + cc];
                    float s0 = sSc[cc], s1 = sSc[cc+1], s2 = sSc[cc+2], s3 = sSc[cc+3];
                    v.x = fmaxf(fmaf(funkey(s0 >= 0.f ? ux.x : un.x), s0, sSh[cc]),   0.f);
                    v.y = fmaxf(fmaf(funkey(s1 >= 0.f ? ux.y : un.y), s1, sSh[cc+1]), 0.f);
                    v.z = fmaxf(fmaf(funkey(s2 >= 0.f ? ux.z : un.z), s2, sSh[cc+2]), 0.f);
                    v.w = fmaxf(fmaf(funkey(s3 >= 0.f ? ux.w : un.w), s3, sSh[cc+3]), 0.f);
                }
            }
            float r0a, r1a, r0b, r1b;
            Ah[m*AS + k4*2]     = hpack(v.x, v.y, r0a, r1a);
            Ah[m*AS + k4*2 + 1] = hpack(v.z, v.w, r0b, r1b);
            Al[m*AS + k4*2]     = hpack2(r0a, r1a);
            Al[m*AS + k4*2 + 1] = hpack2(r0b, r1b);
        }
        // ---- B chunk ----
        for (int e2 = tid; e2 < 32*COUT; e2 += 256) {
            int k2 = e2 / COUT, n = e2 % COUT;
            Bh[k2*BS + n] = Wp[(size_t)(c*32 + k2)*COUT + n];
            Bl[k2*BS + n] = Wp[(size_t)(CIN/2)*COUT + (size_t)(c*32 + k2)*COUT + n];
        }
        __syncthreads();
        // ---- compute ----
#pragma unroll
        for (int kk = 0; kk < 4; kk++) {
            int k2b = kk*8;
            uint32_t ah[MT][4], al[MT][4], bh[4][2], bl[4][2];
#pragma unroll
            for (int mt = 0; mt < MT; mt++) {
                int rb = mbase + mt*16 + gid;
                ah[mt][0] = Ah[rb*AS + k2b + tig];
                ah[mt][1] = Ah[(rb+8)*AS + k2b + tig];
                ah[mt][2] = Ah[rb*AS + k2b + tig + 4];
                ah[mt][3] = Ah[(rb+8)*AS + k2b + tig + 4];
                al[mt][0] = Al[rb*AS + k2b + tig];
                al[mt][1] = Al[(rb+8)*AS + k2b + tig];
                al[mt][2] = Al[rb*AS + k2b + tig + 4];
                al[mt][3] = Al[(rb+8)*AS + k2b + tig + 4];
            }
#pragma unroll
            for (int nt = 0; nt < 4; nt++) {
                int cb = nbase + nt*8 + gid;
                bh[nt][0] = Bh[(k2b + tig)*BS + cb];
                bh[nt][1] = Bh[(k2b + tig + 4)*BS + cb];
                bl[nt][0] = Bl[(k2b + tig)*BS + cb];
                bl[nt][1] = Bl[(k2b + tig + 4)*BS + cb];
            }
#pragma unroll
            for (int mt = 0; mt < MT; mt++)
#pragma unroll
                for (int nt = 0; nt < 4; nt++) {
                    mma16(acc[mt][nt], ah[mt], bh[nt]);
                    mma16(acc[mt][nt], ah[mt], bl[nt]);
                    mma16(acc[mt][nt], al[mt], bh[nt]);
                }
        }
    }
    __syncthreads();
#pragma unroll
    for (int mt = 0; mt < MT; mt++)
#pragma unroll
        for (int nt = 0; nt < 4; nt++) {
            int row = mbase + mt*16 + gid;
            int col = nbase + nt*8 + tig*2;
            float b0 = biasp[col], b1 = biasp[col+1];
            stg[row*(COUT+1) + col]         = acc[mt][nt][0] + b0;
            stg[row*(COUT+1) + col + 1]     = acc[mt][nt][1] + b1;
            stg[(row+8)*(COUT+1) + col]     = acc[mt][nt][2] + b0;
            stg[(row+8)*(COUT+1) + col + 1] = acc[mt][nt][3] + b1;
        }
    __syncthreads();
    if constexpr (MODE == 3) {
        constexpr int G = 256 / COUT, RG = 128 / G;
        int c = tid & (COUT - 1);
        int g = tid / COUT;
        int row0 = g * RG;
        float s = 0.f, q = 0.f, mx = -3.4e38f, mn = 3.4e38f;
        int curp = (r0 + row0) / KKN;
#pragma unroll 4
        for (int rr = 0; rr < RG; rr++) {
            int row = row0 + rr;
            int p = (r0 + row) / KKN;
            if (p != curp) {
                atomicMax(&dmx[(size_t)curp*COUT + c], fkey(mx));
                atomicMin(&dmn[(size_t)curp*COUT + c], fkey(mn));
                curp = p; mx = -3.4e38f; mn = 3.4e38f;
            }
            float v = stg[row*(COUT+1) + c];
            s += v; q += v*v;
            mx = fmaxf(mx, v); mn = fminf(mn, v);
        }
        atomicMax(&dmx[(size_t)curp*COUT + c], fkey(mx));
        atomicMin(&dmn[(size_t)curp*COUT + c], fkey(mn));
        atomicAdd(&sS[c], s); atomicAdd(&sQ2[c], q);
        __syncthreads();
        if (tid < COUT) {
            atomicAdd(&g_sum[sstage][tid], (double)sS[tid]);
            atomicAdd(&g_ssq[sstage][tid], (double)sQ2[tid]);
        }
    } else {
        if constexpr (MODE == 2) {
            int c = tid & 127;
            int g = tid >> 7;
            float s = 0.f, q = 0.f;
#pragma unroll 8
            for (int rr = 0; rr < 64; rr++) {
                float v = stg[(g*64 + rr)*(COUT+1) + c];
                s += v; q += v*v;
            }
            atomicAdd(&sS[c], s); atomicAdd(&sQ2[c], q);
            __syncthreads();
            if (tid < COUT) {
                atomicAdd(&g_sum[sstage][tid], (double)sS[tid]);
                atomicAdd(&g_ssq[sstage][tid], (double)sQ2[tid]);
            }
        }
        float* dst = (MODE == 4) ? dstp : g_h;
        for (int e = tid; e < 128*(COUT/4); e += 256) {
            int r = e / (COUT/4), c4 = e % (COUT/4);
            const float* p = &stg[r*(COUT+1) + c4*4];
            float4 v = make_float4(p[0], p[1], p[2], p[3]);
            *(float4*)&dst[(size_t)(r0 + r)*COUT + c4*4] = v;
        }
    }
}

// ---------------- classifier final -------------------------------------------
__global__ void cls_final_kernel(const float* __restrict__ W2,
                                 const float* __restrict__ B2,
                                 const float* __restrict__ gam,
                                 const float* __restrict__ bet,
                                 float* __restrict__ out) {
    __shared__ float sSc[128], sSh[128];
    affine_init(4, gam, bet, (float)BN_TOTAL, 128, sSc, sSh, threadIdx.x);
    __syncthreads();
    int gw   = (blockIdx.x * blockDim.x + threadIdx.x) >> 5;
    int lane = threadIdx.x & 31;
    const float* hrow = &g_h[(size_t)gw * 128];
    float p = 0.f;
#pragma unroll
    for (int q = 0; q < 4; q++) {
        int c = lane + 32*q;
        float v = fmaxf(fmaf(hrow[c], sSc[c], sSh[c]), 0.f);
        p = fmaf(v, W2[c], p);
    }
#pragma unroll
    for (int o = 16; o > 0; o >>= 1) p += __shfl_down_sync(0xffffffffu, p, o);
    if (lane == 0) out[gw] = p + B2[0];
}

// ---------------- host orchestration ----------------------------------------
extern "C" void kernel_launch(void* const* d_in, const int* in_sizes, int n_in,
                              void* d_out, int out_size) {
    const float* x      = (const float*)d_in[0];
    const float* c1_w1  = (const float*)d_in[1];
    const float* c1_b1  = (const float*)d_in[2];
    const float* c1_g1  = (const float*)d_in[3];
    const float* c1_be1 = (const float*)d_in[4];
    const float* c1_w2  = (const float*)d_in[5];
    const float* c1_b2  = (const float*)d_in[6];
    const float* c1_g2  = (const float*)d_in[7];
    const float* c1_be2 = (const float*)d_in[8];
    const float* c2_w1  = (const float*)d_in[9];
    const float* c2_b1  = (const float*)d_in[10];
    const float* c2_g1  = (const float*)d_in[11];
    const float* c2_be1 = (const float*)d_in[12];
    const float* c2_w2  = (const float*)d_in[13];
    const float* c2_b2  = (const float*)d_in[14];
    const float* c2_g2  = (const float*)d_in[15];
    const float* c2_be2 = (const float*)d_in[16];
    const float* cls_w1 = (const float*)d_in[17];
    const float* cls_b1 = (const float*)d_in[18];
    const float* cls_g1 = (const float*)d_in[19];
    const float* cls_be1= (const float*)d_in[20];
    const float* cls_w2 = (const float*)d_in[21];
    const float* cls_b2 = (const float*)d_in[22];
    float* out = (float*)d_out;

    int* idx_ptr;   cudaGetSymbolAddress((void**)&idx_ptr, g_idx);
    uint32_t* wimg; cudaGetSymbolAddress((void**)&wimg, g_wimg);
    float *p1, *q1, *p2, *q2, *zero, *x1;
    uint32_t *x1mx, *x1mn, *x2mx, *x2mn;
    cudaGetSymbolAddress((void**)&p1, g_P1);
    cudaGetSymbolAddress((void**)&q1, g_Q1);
    cudaGetSymbolAddress((void**)&p2, g_P2);
    cudaGetSymbolAddress((void**)&q2, g_Q2);
    cudaGetSymbolAddress((void**)&zero, g_zero);
    cudaGetSymbolAddress((void**)&x1, g_x1);
    cudaGetSymbolAddress((void**)&x1mx, g_x1mx);
    cudaGetSymbolAddress((void**)&x1mn, g_x1mn);
    cudaGetSymbolAddress((void**)&x2mx, g_x2mx);
    cudaGetSymbolAddress((void**)&x2mn, g_x2mn);

    const int SMB128 = (2*128*36 + 2*32*136) * 4;                       // 71680
    const int SMB64  = (2*128*36 + 2*32*72)  * 4;                       // 55296
    const int SMKNN  = (2*128*36 + 2*32*136 + 128*133 + 256) * 4;       // 140800
    cudaFuncSetAttribute(tgemm_kernel<64,64,3>,   cudaFuncAttributeMaxDynamicSharedMemorySize, SMB64);
    cudaFuncSetAttribute(tgemm_kernel<64,128,4>,  cudaFuncAttributeMaxDynamicSharedMemorySize, SMB128);
    cudaFuncSetAttribute(tgemm_kernel<128,128,3>, cudaFuncAttributeMaxDynamicSharedMemorySize, SMB128);
    cudaFuncSetAttribute(tgemm_kernel<192,128,2>, cudaFuncAttributeMaxDynamicSharedMemorySize, SMB128);
    cudaFuncSetAttribute(knn64_kernel,            cudaFuncAttributeMaxDynamicSharedMemorySize, SMKNN);

    // launch order: #4 (1-based) = tgemm<64,64,3> for the ncu capture (control)
    front_kernel<<<14568, 256>>>(x, idx_ptr, c1_w1, c1_b1, c1_w2, c2_w1, c2_w2,
                                 cls_w1, wimg);                                     // 1
    stats1pt_kernel<64><<<1024, 256>>>(p1, q1, 0, 0);                               // 2
    stats1pt_kernel<64><<<1024, 256>>>(p1, q1, 0, BN_TOTAL/2);                      // 3
    tgemm_kernel<64,64,3><<<R_EDGE/128, 256, SMB64>>>(1, 0, wimg + OFF_C1L2, c1_b2,
        c1_g1, c1_be1, (float)R_EDGE, p1, q1, nullptr, x1mx, x1mn,
        nullptr, nullptr, nullptr);                                                 // 4 <- ncu
    finalize_x1_kernel<<<BN_TOTAL*64/256, 256>>>(c1_g2, c1_be2);                    // 5
    knn64_kernel<<<BB*32, 256, SMKNN>>>(idx_ptr);                                   // 6
    tgemm_kernel<64,128,4><<<2*(BN_TOTAL/128), 256, SMB128>>>(-1, 0, wimg + OFF_P2, c2_b1,
        nullptr, nullptr, 0.f, x1, nullptr, p2, nullptr, nullptr,
        wimg + OFF_Q2, zero, q2);                                                   // 7
    stats1pt_kernel<128><<<4096, 256>>>(p2, q2, 2, 0);                              // 8
    tgemm_kernel<128,128,3><<<R_EDGE/128, 256, SMB128>>>(3, 2, wimg + OFF_C2L2, c2_b2,
        c2_g1, c2_be1, (float)R_EDGE, p2, q2, nullptr, x2mx, x2mn,
        nullptr, nullptr, nullptr);                                                 // 9
    tgemm_kernel<192,128,2><<<BN_TOTAL/128, 256, SMB128>>>(4, 3, wimg + OFF_CLS, cls_b1,
        c2_g2, c2_be2, (float)R_EDGE, x1, nullptr, nullptr, x2mx, x2mn,
        nullptr, nullptr, nullptr);                                                 // 10
    cls_final_kernel<<<BN_TOTAL/8, 256>>>(cls_w2, cls_b2, cls_g1, cls_be1, out);    // 11
}

// round 16
// speedup vs baseline: 1.0512x; 1.0512x over previous
#include <cuda_runtime.h>
#include <cuda_fp16.h>
#include <math.h>
#include <stdint.h>

#define BB 8
#define NN 4096
#define KKN 20
#define BN_TOTAL (BB*NN)          // 32768
#define R_EDGE (BB*NN*KKN)        // 655360
#define EPSI 1e-5f

// ---------------- scratch (device globals; no allocation allowed) ------------
__device__ float    g_h[(size_t)BN_TOTAL*128];
__device__ float    g_x1[BN_TOTAL*64];
__device__ float    g_P1[BN_TOTAL*64],  g_Q1[BN_TOTAL*64];
__device__ float    g_P2[BN_TOTAL*128], g_Q2[BN_TOTAL*128];
__device__ uint32_t g_x1mx[BN_TOTAL*64],  g_x1mn[BN_TOTAL*64];
__device__ uint32_t g_x2mx[BN_TOTAL*128], g_x2mn[BN_TOTAL*128];
__device__ int      g_idx[R_EDGE];
__device__ double   g_sum[5][128];
__device__ double   g_ssq[5][128];
__device__ uint32_t g_wimg[61440];
__device__ float    g_zero[128];

#define OFF_C1L2 0
#define OFF_P2   4096
#define OFF_Q2   12288
#define OFF_C2L2 20480
#define OFF_CLS  36864

// ---------------- helpers -----------------------------------------------------
__device__ __forceinline__ uint32_t hpack(float v0, float v1, float& r0, float& r1) {
    __half h0 = __float2half_rn(v0), h1 = __float2half_rn(v1);
    r0 = v0 - __half2float(h0);
    r1 = v1 - __half2float(h1);
    __half2 p = __halves2half2(h0, h1);
    return *(uint32_t*)&p;
}
__device__ __forceinline__ uint32_t hpack2(float v0, float v1) {
    __half2 p = __halves2half2(__float2half_rn(v0), __float2half_rn(v1));
    return *(uint32_t*)&p;
}
__device__ __forceinline__ void mma16(float* c, const uint32_t* a, const uint32_t* b) {
    asm volatile("mma.sync.aligned.m16n8k16.row.col.f32.f16.f16.f32 "
        "{%0,%1,%2,%3}, {%4,%5,%6,%7}, {%8,%9}, {%0,%1,%2,%3};"
        : "+f"(c[0]), "+f"(c[1]), "+f"(c[2]), "+f"(c[3])
        : "r"(a[0]), "r"(a[1]), "r"(a[2]), "r"(a[3]), "r"(b[0]), "r"(b[1]));
}
__device__ __forceinline__ void affine_init(int stage, const float* gam, const float* bet,
                                            float n, int cout, float* sSc, float* sSh, int tid) {
    if (tid < cout) {
        double mean = g_sum[stage][tid] / (double)n;
        double var  = g_ssq[stage][tid] / (double)n - mean*mean;
        float  s    = gam[tid] / sqrtf((float)var + EPSI);
        sSc[tid] = s;
        sSh[tid] = bet[tid] - (float)mean * s;
    }
}
__device__ __forceinline__ uint32_t fkey(float f) {
    uint32_t u = __float_as_uint(f);
    return u ^ ((u >> 31) ? 0xffffffffu : 0x80000000u);
}
__device__ __forceinline__ float funkey(uint32_t u) {
    return __uint_as_float(u ^ ((u >> 31) ? 0x80000000u : 0xffffffffu));
}

// ---------------- knn for C=4: 1 thread/point (register lists, no merge) ------
__global__ void knn4_kernel(const float* __restrict__ Xin, int* __restrict__ out_idx) {
    constexpr int TI = 128, TJ = 128;
    __shared__ float4 sxj[TJ];
    __shared__ float  sx2[TJ];
    const float4* X4 = (const float4*)Xin;

    if (blockIdx.x == 0) {
        for (int t = threadIdx.x; t < 640; t += TI) {
            (&g_sum[0][0])[t] = 0.0; (&g_ssq[0][0])[t] = 0.0;
        }
    }
    int b = blockIdx.x / (NN / TI);
    int i = (blockIdx.x % (NN / TI)) * TI + threadIdx.x;

    float4 xi = X4[(size_t)b*NN + i];
    float x2i = xi.x*xi.x + xi.y*xi.y + xi.z*xi.z + xi.w*xi.w;

    float td[KKN]; int ti[KKN];
#pragma unroll
    for (int s = 0; s < KKN; s++) { td[s] = 3.4e38f; ti[s] = 0; }

    for (int j0 = 0; j0 < NN; j0 += TJ) {
        __syncthreads();
        {
            float4 v = X4[(size_t)b*NN + j0 + threadIdx.x];
            sxj[threadIdx.x] = v;
            sx2[threadIdx.x] = v.x*v.x + v.y*v.y + v.z*v.z + v.w*v.w;
        }
        __syncthreads();
        for (int jj = 0; jj < TJ; jj++) {
            float4 v = sxj[jj];
            float dot = xi.x*v.x + xi.y*v.y + xi.z*v.z + xi.w*v.w;
            float d = x2i + sx2[jj] - 2.0f*dot;
            if (d < td[KKN-1]) {
                td[KKN-1] = d; ti[KKN-1] = j0 + jj;
#pragma unroll
                for (int s = KKN-1; s > 0; s--) {
                    if (td[s] < td[s-1]) {
                        float t0 = td[s]; td[s] = td[s-1]; td[s-1] = t0;
                        int   u0 = ti[s]; ti[s] = ti[s-1]; ti[s-1] = u0;
                    }
                }
            }
        }
    }
#pragma unroll
    for (int s = 0; s < KKN; s++) out_idx[(size_t)(b*NN + i)*KKN + s] = ti[s];
}

// ---------------- prep: pq1 + weight prep + max/min buffer init ---------------
__global__ void prep_kernel(const float* __restrict__ X, const float* __restrict__ c1w1,
                            const float* __restrict__ c1b1, const float* __restrict__ c1w2,
                            const float* __restrict__ c2w1, const float* __restrict__ c2w2,
                            const float* __restrict__ clsw1, uint32_t* __restrict__ wimg) {
    __shared__ float sWd[4*64], sWb[4*64], sB[64];
    int bid = blockIdx.x, tid = threadIdx.x;
    if (bid < 8192) {
        {
            int ci = tid >> 6, c = tid & 63;
            sWd[ci*64+c] = c1w1[ci*64+c] - c1w1[(ci+4)*64+c];
            sWb[ci*64+c] = c1w1[(ci+4)*64+c];
        }
        if (tid < 64) sB[tid] = c1b1[tid];
        __syncthreads();
        int c = tid & 63;
        int bn = bid*4 + (tid >> 6);
        float4 x = ((const float4*)X)[bn];
        float p = sB[c] + x.x*sWd[c] + x.y*sWd[64+c] + x.z*sWd[128+c] + x.w*sWd[192+c];
        float q =         x.x*sWb[c] + x.y*sWb[64+c] + x.z*sWb[128+c] + x.w*sWb[192+c];
        g_P1[(size_t)bn*64 + c] = p;
        g_Q1[(size_t)bn*64 + c] = q;
    } else if (bid < 8296) {
        int wb = bid - 8192;
        if (wb < 8) {
            int t = wb*256 + tid;
            if (t < 32*64) {
                int k2 = t / 64, n = t % 64;
                float w0 = c1w2[(size_t)(2*k2)*64 + n], w1 = c1w2[(size_t)(2*k2+1)*64 + n];
                float r0, r1;
                wimg[OFF_C1L2 + t] = hpack(w0, w1, r0, r1);
                wimg[OFF_C1L2 + 32*64 + t] = hpack2(r0, r1);
            }
        } else if (wb < 24) {
            int t = (wb-8)*256 + tid;
            if (t < 32*128) {
                int k2 = t / 128, n = t % 128;
                float wt0 = c2w1[(size_t)(2*k2)*128 + n],    wt1 = c2w1[(size_t)(2*k2+1)*128 + n];
                float wb0 = c2w1[(size_t)(2*k2+64)*128 + n], wb1 = c2w1[(size_t)(2*k2+65)*128 + n];
                float r0, r1;
                wimg[OFF_P2 + t] = hpack(wt0 - wb0, wt1 - wb1, r0, r1);
                wimg[OFF_P2 + 32*128 + t] = hpack2(r0, r1);
                wimg[OFF_Q2 + t] = hpack(wb0, wb1, r0, r1);
                wimg[OFF_Q2 + 32*128 + t] = hpack2(r0, r1);
            }
        } else if (wb < 56) {
            int t = (wb-24)*256 + tid;
            if (t < 64*128) {
                int k2 = t / 128, n = t % 128;
                float w0 = c2w2[(size_t)(2*k2)*128 + n], w1 = c2w2[(size_t)(2*k2+1)*128 + n];
                float r0, r1;
                wimg[OFF_C2L2 + t] = hpack(w0, w1, r0, r1);
                wimg[OFF_C2L2 + 64*128 + t] = hpack2(r0, r1);
            }
        } else {
            int t = (wb-56)*256 + tid;
            if (t < 96*128) {
                int k2 = t / 128, n = t % 128;
                float w0 = clsw1[(size_t)(2*k2)*128 + n], w1 = clsw1[(size_t)(2*k2+1)*128 + n];
                float r0, r1;
                wimg[OFF_CLS + t] = hpack(w0, w1, r0, r1);
                wimg[OFF_CLS + 96*128 + t] = hpack2(r0, r1);
            }
        }
    } else {
        int rel = bid - 8296;
        uint32_t* dst; uint32_t val;
        size_t off;
        if (rel < 1024)      { dst = g_x1mx; val = 0u;          off = (size_t)rel*2048; }
        else if (rel < 2048) { dst = g_x1mn; val = 0xffffffffu; off = (size_t)(rel-1024)*2048; }
        else if (rel < 4096) { dst = g_x2mx; val = 0u;          off = (size_t)(rel-2048)*2048; }
        else                 { dst = g_x2mn; val = 0xffffffffu; off = (size_t)(rel-4096)*2048; }
        uint4 v4 = make_uint4(val, val, val, val);
        uint4* d4 = (uint4*)(dst + off);
#pragma unroll
        for (int u = 0; u < 2; u++) d4[tid + 256*u] = v4;
    }
}

// ---------------- layer-1 BN stats from P,Q over edges ------------------------
template<int COUT>
__global__ void stats1_kernel(const float* __restrict__ P, const float* __restrict__ Q,
                              int sstage) {
    constexpr int G = 256 / COUT;
    constexpr int EPB = 320;
    __shared__ float sS[COUT], sQ2[COUT];
    int tid = threadIdx.x;
    int c = tid & (COUT-1), g = tid / COUT;
    if (tid < COUT) { sS[tid] = 0.f; sQ2[tid] = 0.f; }
    __syncthreads();
    int r0 = blockIdx.x * EPB;
    float s = 0.f, q = 0.f;
    for (int e = g; e < EPB; e += G) {
        int r = r0 + e;
        unsigned bn = (unsigned)r / KKN;
        int b = bn >> 12;
        int j = g_idx[r];
        float h = P[(size_t)bn*COUT + c] + Q[((size_t)(b<<12) + j)*COUT + c];
        s += h; q += h*h;
    }
    atomicAdd(&sS[c], s); atomicAdd(&sQ2[c], q);
    __syncthreads();
    if (tid < COUT) {
        atomicAdd(&g_sum[sstage][tid], (double)sS[tid]);
        atomicAdd(&g_ssq[sstage][tid], (double)sQ2[tid]);
    }
}

// ---------------- finalize x1: relu(bn(max/min)) ------------------------------
__global__ void finalize_x1_kernel(const float* __restrict__ gam,
                                   const float* __restrict__ bet) {
    __shared__ float sSc[64], sSh[64];
    affine_init(1, gam, bet, (float)R_EDGE, 64, sSc, sSh, threadIdx.x);
    __syncthreads();
    int t = blockIdx.x*256 + threadIdx.x;
    int c = t & 63;
    float s = sSc[c];
    uint32_t u = (s >= 0.f) ? g_x1mx[t] : g_x1mn[t];
    g_x1[t] = fmaxf(fmaf(funkey(u), s, sSh[c]), 0.f);
}

// ---------------- knn for C=64: 128-row CTAs, smem-only merge -----------------
__global__ void __launch_bounds__(256, 1)
knn64_kernel(int* __restrict__ out_idx) {
    extern __shared__ uint32_t smu[];
    constexpr int AS = 36, BS = 136;
    uint32_t* XiH = smu;                     // [128][36]
    uint32_t* XiL = smu + 128*AS;
    uint32_t* XjH = smu + 2*128*AS;          // [32][136]
    uint32_t* XjL = XjH + 32*BS;
    float* dist = (float*)(XjL + 32*BS);     // [128][133]
    float* x2i  = dist + 128*133;            // [128]
    float* x2j  = x2i + 128;                 // [128]

    int tid = threadIdx.x, wid = tid >> 5, lane = tid & 31;
    int gid = lane >> 2, tig = lane & 3;
    int b  = blockIdx.x >> 5;
    int i0 = (blockIdx.x & 31) * 128;
    int mbase = (wid >> 2) * 64;
    int nbase = (wid & 3) * 32;
    int rrow = tid & 127, hf = tid >> 7;

    {
        const float4* row = (const float4*)&g_x1[(size_t)(b*NN + i0 + rrow)*64];
#pragma unroll
        for (int qq = 0; qq < 8; qq++) {
            int q = hf*8 + qq;
            float4 v = row[q];
            float r0, r1;
            XiH[rrow*AS + 2*q]   = hpack(v.x, v.y, r0, r1);
            XiL[rrow*AS + 2*q]   = hpack2(r0, r1);
            XiH[rrow*AS + 2*q+1] = hpack(v.z, v.w, r0, r1);
            XiL[rrow*AS + 2*q+1] = hpack2(r0, r1);
        }
    }
    if (tid < 128) {
        const float4* row = (const float4*)&g_x1[(size_t)(b*NN + i0 + tid)*64];
        float s = 0.f;
#pragma unroll
        for (int q = 0; q < 16; q++) {
            float4 v = row[q];
            s += v.x*v.x + v.y*v.y + v.z*v.z + v.w*v.w;
        }
        x2i[tid] = s;
    }

    float td[KKN]; int ti[KKN];
#pragma unroll
    for (int s = 0; s < KKN; s++) { td[s] = 3.4e38f; ti[s] = 0; }

    for (int jt = 0; jt < 32; jt++) {
        __syncthreads();
        {
            const float4* row = (const float4*)&g_x1[(size_t)(b*NN + jt*128 + rrow)*64];
#pragma unroll
            for (int qq = 0; qq < 8; qq++) {
                int q = hf*8 + qq;
                float4 v = row[q];
                float r0, r1;
                XjH[(2*q)*BS + rrow]   = hpack(v.x, v.y, r0, r1);
                XjL[(2*q)*BS + rrow]   = hpack2(r0, r1);
                XjH[(2*q+1)*BS + rrow] = hpack(v.z, v.w, r0, r1);
                XjL[(2*q+1)*BS + rrow] = hpack2(r0, r1);
            }
        }
        if (tid < 128) {
            const float4* row = (const float4*)&g_x1[(size_t)(b*NN + jt*128 + tid)*64];
            float s = 0.f;
#pragma unroll
            for (int q = 0; q < 16; q++) {
                float4 v = row[q];
                s += v.x*v.x + v.y*v.y + v.z*v.z + v.w*v.w;
            }
            x2j[tid] = s;
        }
        __syncthreads();

        float acc[4][4][4];
#pragma unroll
        for (int mt = 0; mt < 4; mt++)
#pragma unroll
            for (int nt = 0; nt < 4; nt++)
#pragma unroll
                for (int u = 0; u < 4; u++) acc[mt][nt][u] = 0.f;

#pragma unroll
        for (int kk = 0; kk < 4; kk++) {
            int k2b = kk*8;
            uint32_t ah[4][4], al[4][4], bh[4][2], bl[4][2];
#pragma unroll
            for (int mt = 0; mt < 4; mt++) {
                int rb = mbase + mt*16 + gid;
                ah[mt][0] = XiH[rb*AS + k2b + tig];
                ah[mt][1] = XiH[(rb+8)*AS + k2b + tig];
                ah[mt][2] = XiH[rb*AS + k2b + tig + 4];
                ah[mt][3] = XiH[(rb+8)*AS + k2b + tig + 4];
                al[mt][0] = XiL[rb*AS + k2b + tig];
                al[mt][1] = XiL[(rb+8)*AS + k2b + tig];
                al[mt][2] = XiL[rb*AS + k2b + tig + 4];
                al[mt][3] = XiL[(rb+8)*AS + k2b + tig + 4];
            }
#pragma unroll
            for (int nt = 0; nt < 4; nt++) {
                int cb = nbase + nt*8 + gid;
                bh[nt][0] = XjH[(k2b + tig)*BS + cb];
                bh[nt][1] = XjH[(k2b + tig + 4)*BS + cb];
                bl[nt][0] = XjL[(k2b + tig)*BS + cb];
                bl[nt][1] = XjL[(k2b + tig + 4)*BS + cb];
            }
#pragma unroll
            for (int mt = 0; mt < 4; mt++)
#pragma unroll
                for (int nt = 0; nt < 4; nt++) {
                    mma16(acc[mt][nt], ah[mt], bh[nt]);
                    mma16(acc[mt][nt], ah[mt], bl[nt]);
                    mma16(acc[mt][nt], al[mt], bh[nt]);
                    mma16(acc[mt][nt], al[mt], bl[nt]);
                }
        }
#pragma unroll
        for (int mt = 0; mt < 4; mt++)
#pragma unroll
            for (int nt = 0; nt < 4; nt++) {
                int row = mbase + mt*16 + gid;
                int col = nbase + nt*8 + tig*2;
                dist[row*133 + col]         = acc[mt][nt][0];
                dist[row*133 + col + 1]     = acc[mt][nt][1];
                dist[(row+8)*133 + col]     = acc[mt][nt][2];
                dist[(row+8)*133 + col + 1] = acc[mt][nt][3];
            }
        __syncthreads();
        {
            float xi2 = x2i[rrow];
            const float* drow = &dist[rrow*133 + hf*64];
            const float* xj2 = x2j + hf*64;
            for (int jj = 0; jj < 64; jj++) {
                float d = xi2 + xj2[jj] - 2.0f*drow[jj];
                if (d < td[KKN-1]) {
                    td[KKN-1] = d; ti[KKN-1] = jt*128 + hf*64 + jj;
#pragma unroll
                    for (int s = KKN-1; s > 0; s--) {
                        if (td[s] < td[s-1]) {
                            float t0 = td[s]; td[s] = td[s-1]; td[s-1] = t0;
                            int   u0 = ti[s]; ti[s] = ti[s-1]; ti[s-1] = u0;
                        }
                    }
                }
            }
        }
    }
    __syncthreads();
    float* md = dist;                      // [128][2][20]
    int*   mi = (int*)(dist + 5120);       // [128][2][20]
    {
        int base = rrow*40 + hf*20;
#pragma unroll
        for (int s = 0; s < KKN; s++) { md[base + s] = td[s]; mi[base + s] = ti[s]; }
    }
    __syncthreads();
    if (hf == 0) {
        const float* L = &md[rrow*40];
        const int*   I = &mi[rrow*40];
        int a = 0, bb2 = 0;
        int* orow = &out_idx[(size_t)(b*NN + i0 + rrow)*KKN];
#pragma unroll
        for (int s = 0; s < KKN; s++) {
            float da = L[a], db = L[20 + bb2];
            int ja = I[a],  jb = I[20 + bb2];
            bool takeA = (da < db) || (da == db && ja < jb);
            orow[s] = takeA ? ja : jb;
            if (takeA) a++; else bb2++;
        }
    }
}

// ================= fp16-split warp-MMA GEMM + fused epilogue =================
template<int CIN, int COUT, int MODE>
__global__ void __launch_bounds__(256, ((COUT == 64) ? 3 : 2))
tgemm_kernel(int sstage, int pstage, const uint32_t* __restrict__ Wimg,
             const float* __restrict__ bias,
             const float* __restrict__ gam, const float* __restrict__ bet, float nstat,
             const float* __restrict__ Pin, const float* __restrict__ Qin,
             float* __restrict__ Hout,
             uint32_t* __restrict__ dmx, uint32_t* __restrict__ dmn,
             const uint32_t* __restrict__ Wimg2, const float* __restrict__ bias2,
             float* __restrict__ Hout2) {
    extern __shared__ uint32_t smu[];
    constexpr int NCH = CIN / 64;
    constexpr int AS  = 36;
    constexpr int BS  = COUT + 8;
    constexpr int MT  = (COUT == 128) ? 4 : 2;
    uint32_t* Ah = smu;
    uint32_t* Al = smu + 128*AS;
    uint32_t* Bh = smu + 2*128*AS;
    uint32_t* Bl = Bh + 32*BS;
    float* stg = (float*)smu;
    __shared__ float sSc[128], sSh[128];
    __shared__ float sS[128], sQ2[128];

    int tid = threadIdx.x, wid = tid >> 5, lane = tid & 31;
    int gid = lane >> 2, tig = lane & 3;

    const uint32_t* Wp = Wimg;
    const float* biasp = bias;
    float* dstp = Hout;
    int r0;
    if constexpr (MODE == 4) {
        int half = gridDim.x >> 1;
        bool sec = (int)blockIdx.x >= half;
        Wp = sec ? Wimg2 : Wimg;
        biasp = sec ? bias2 : bias;
        dstp = sec ? Hout2 : Hout;
        r0 = (sec ? blockIdx.x - half : blockIdx.x) * 128;
    } else {
        r0 = blockIdx.x * 128;
    }

    if (tid < COUT) { sS[tid] = 0.f; sQ2[tid] = 0.f; }
    if constexpr (MODE == 3 || MODE == 2) {
        affine_init(pstage, gam, bet, nstat, (MODE == 3) ? CIN : 128, sSc, sSh, tid);
        __syncthreads();
    }

    int mbase = (COUT == 128) ? (wid >> 2) * 64 : (wid >> 1) * 32;
    int nbase = (COUT == 128) ? (wid & 3) * 32  : (wid & 1) * 32;

    float acc[MT][4][4];
#pragma unroll
    for (int mt = 0; mt < MT; mt++)
#pragma unroll
        for (int nt = 0; nt < 4; nt++)
#pragma unroll
            for (int u = 0; u < 4; u++) acc[mt][nt][u] = 0.f;

    for (int c = 0; c < NCH; c++) {
        if (c) __syncthreads();
        // ---- A chunk (float4-vectorized) ----
        for (int e4 = tid; e4 < 128*16; e4 += 256) {
            int m = e4 >> 4, k4 = e4 & 15;
            int kc = c*64 + k4*4;
            int r = r0 + m;
            float4 v;
            if constexpr (MODE == 3) {
                unsigned bn = (unsigned)r / KKN;
                int b = bn >> 12;
                int j = g_idx[r];
                float4 p = *(const float4*)&Pin[(size_t)bn*CIN + kc];
                float4 q = *(const float4*)&Qin[((size_t)(b<<12) + j)*CIN + kc];
                v.x = fmaxf(fmaf(p.x + q.x, sSc[kc],   sSh[kc]),   0.f);
                v.y = fmaxf(fmaf(p.y + q.y, sSc[kc+1], sSh[kc+1]), 0.f);
                v.z = fmaxf(fmaf(p.z + q.z, sSc[kc+2], sSh[kc+2]), 0.f);
                v.w = fmaxf(fmaf(p.w + q.w, sSc[kc+3], sSh[kc+3]), 0.f);
            } else if constexpr (MODE == 4) {
                v = *(const float4*)&Pin[(size_t)r*CIN + kc];
            } else {
                if (kc < 64) {
                    v = *(const float4*)&Pin[(size_t)r*64 + kc];
                } else {
                    int cc = kc - 64;
                    const uint4 ux = *(const uint4*)&dmx[(size_t)r*128 + cc];
                    const uint4 un = *(const uint4*)&dmn[(size_t)r*128 + cc];
                    float s0 = sSc[cc], s1 = sSc[cc+1], s2 = sSc[cc+2], s3 = sSc[cc+3];
                    v.x = fmaxf(fmaf(funkey(s0 >= 0.f ? ux.x : un.x), s0, sSh[cc]),   0.f);
                    v.y = fmaxf(fmaf(funkey(s1 >= 0.f ? ux.y : un.y), s1, sSh[cc+1]), 0.f);
                    v.z = fmaxf(fmaf(funkey(s2 >= 0.f ? ux.z : un.z), s2, sSh[cc+2]), 0.f);
                    v.w = fmaxf(fmaf(funkey(s3 >= 0.f ? ux.w : un.w), s3, sSh[cc+3]), 0.f);
                }
            }
            float r0a, r1a, r0b, r1b;
            Ah[m*AS + k4*2]     = hpack(v.x, v.y, r0a, r1a);
            Ah[m*AS + k4*2 + 1] = hpack(v.z, v.w, r0b, r1b);
            Al[m*AS + k4*2]     = hpack2(r0a, r1a);
            Al[m*AS + k4*2 + 1] = hpack2(r0b, r1b);
        }
        // ---- B chunk ----
        for (int e2 = tid; e2 < 32*COUT; e2 += 256) {
            int k2 = e2 / COUT, n = e2 % COUT;
            Bh[k2*BS + n] = Wp[(size_t)(c*32 + k2)*COUT + n];
            Bl[k2*BS + n] = Wp[(size_t)(CIN/2)*COUT + (size_t)(c*32 + k2)*COUT + n];
        }
        __syncthreads();
        // ---- compute ----
#pragma unroll
        for (int kk = 0; kk < 4; kk++) {
            int k2b = kk*8;
            uint32_t ah[MT][4], al[MT][4], bh[4][2], bl[4][2];
#pragma unroll
            for (int mt = 0; mt < MT; mt++) {
                int rb = mbase + mt*16 + gid;
                ah[mt][0] = Ah[rb*AS + k2b + tig];
                ah[mt][1] = Ah[(rb+8)*AS + k2b + tig];
                ah[mt][2] = Ah[rb*AS + k2b + tig + 4];
                ah[mt][3] = Ah[(rb+8)*AS + k2b + tig + 4];
                al[mt][0] = Al[rb*AS + k2b + tig];
                al[mt][1] = Al[(rb+8)*AS + k2b + tig];
                al[mt][2] = Al[rb*AS + k2b + tig + 4];
                al[mt][3] = Al[(rb+8)*AS + k2b + tig + 4];
            }
#pragma unroll
            for (int nt = 0; nt < 4; nt++) {
                int cb = nbase + nt*8 + gid;
                bh[nt][0] = Bh[(k2b + tig)*BS + cb];
                bh[nt][1] = Bh[(k2b + tig + 4)*BS + cb];
                bl[nt][0] = Bl[(k2b + tig)*BS + cb];
                bl[nt][1] = Bl[(k2b + tig + 4)*BS + cb];
            }
#pragma unroll
            for (int mt = 0; mt < MT; mt++)
#pragma unroll
                for (int nt = 0; nt < 4; nt++) {
                    mma16(acc[mt][nt], ah[mt], bh[nt]);
                    mma16(acc[mt][nt], ah[mt], bl[nt]);
                    mma16(acc[mt][nt], al[mt], bh[nt]);
                }
        }
    }
    __syncthreads();
#pragma unroll
    for (int mt = 0; mt < MT; mt++)
#pragma unroll
        for (int nt = 0; nt < 4; nt++) {
            int row = mbase + mt*16 + gid;
            int col = nbase + nt*8 + tig*2;
            float b0 = biasp[col], b1 = biasp[col+1];
            stg[row*(COUT+1) + col]         = acc[mt][nt][0] + b0;
            stg[row*(COUT+1) + col + 1]     = acc[mt][nt][1] + b1;
            stg[(row+8)*(COUT+1) + col]     = acc[mt][nt][2] + b0;
            stg[(row+8)*(COUT+1) + col + 1] = acc[mt][nt][3] + b1;
        }
    __syncthreads();
    if constexpr (MODE == 3) {
        constexpr int G = 256 / COUT, RG = 128 / G;
        int c = tid & (COUT - 1);
        int g = tid / COUT;
        int row0 = g * RG;
        float s = 0.f, q = 0.f, mx = -3.4e38f, mn = 3.4e38f;
        int curp = (r0 + row0) / KKN;
#pragma unroll 4
        for (int rr = 0; rr < RG; rr++) {
            int row = row0 + rr;
            int p = (r0 + row) / KKN;
            if (p != curp) {
                atomicMax(&dmx[(size_t)curp*COUT + c], fkey(mx));
                atomicMin(&dmn[(size_t)curp*COUT + c], fkey(mn));
                curp = p; mx = -3.4e38f; mn = 3.4e38f;
            }
            float v = stg[row*(COUT+1) + c];
            s += v; q += v*v;
            mx = fmaxf(mx, v); mn = fminf(mn, v);
        }
        atomicMax(&dmx[(size_t)curp*COUT + c], fkey(mx));
        atomicMin(&dmn[(size_t)curp*COUT + c], fkey(mn));
        atomicAdd(&sS[c], s); atomicAdd(&sQ2[c], q);
        __syncthreads();
        if (tid < COUT) {
            atomicAdd(&g_sum[sstage][tid], (double)sS[tid]);
            atomicAdd(&g_ssq[sstage][tid], (double)sQ2[tid]);
        }
    } else {
        if constexpr (MODE == 2) {
            int c = tid & 127;
            int g = tid >> 7;
            float s = 0.f, q = 0.f;
#pragma unroll 8
            for (int rr = 0; rr < 64; rr++) {
                float v = stg[(g*64 + rr)*(COUT+1) + c];
                s += v; q += v*v;
            }
            atomicAdd(&sS[c], s); atomicAdd(&sQ2[c], q);
            __syncthreads();
            if (tid < COUT) {
                atomicAdd(&g_sum[sstage][tid], (double)sS[tid]);
                atomicAdd(&g_ssq[sstage][tid], (double)sQ2[tid]);
            }
        }
        float* dst = (MODE == 4) ? dstp : g_h;
        for (int e = tid; e < 128*(COUT/4); e += 256) {
            int r = e / (COUT/4), c4 = e % (COUT/4);
            const float* p = &stg[r*(COUT+1) + c4*4];
            float4 v = make_float4(p[0], p[1], p[2], p[3]);
            *(float4*)&dst[(size_t)(r0 + r)*COUT + c4*4] = v;
        }
    }
}

// ---------------- classifier final -------------------------------------------
__global__ void cls_final_kernel(const float* __restrict__ W2,
                                 const float* __restrict__ B2,
                                 const float* __restrict__ gam,
                                 const float* __restrict__ bet,
                                 float* __restrict__ out) {
    __shared__ float sSc[128], sSh[128];
    affine_init(4, gam, bet, (float)BN_TOTAL, 128, sSc, sSh, threadIdx.x);
    __syncthreads();
    int gw   = (blockIdx.x * blockDim.x + threadIdx.x) >> 5;
    int lane = threadIdx.x & 31;
    const float* hrow = &g_h[(size_t)gw * 128];
    float p = 0.f;
#pragma unroll
    for (int q = 0; q < 4; q++) {
        int c = lane + 32*q;
        float v = fmaxf(fmaf(hrow[c], sSc[c], sSh[c]), 0.f);
        p = fmaf(v, W2[c], p);
    }
#pragma unroll
    for (int o = 16; o > 0; o >>= 1) p += __shfl_down_sync(0xffffffffu, p, o);
    if (lane == 0) out[gw] = p + B2[0];
}

// ---------------- host orchestration ----------------------------------------
extern "C" void kernel_launch(void* const* d_in, const int* in_sizes, int n_in,
                              void* d_out, int out_size) {
    const float* x      = (const float*)d_in[0];
    const float* c1_w1  = (const float*)d_in[1];
    const float* c1_b1  = (const float*)d_in[2];
    const float* c1_g1  = (const float*)d_in[3];
    const float* c1_be1 = (const float*)d_in[4];
    const float* c1_w2  = (const float*)d_in[5];
    const float* c1_b2  = (const float*)d_in[6];
    const float* c1_g2  = (const float*)d_in[7];
    const float* c1_be2 = (const float*)d_in[8];
    const float* c2_w1  = (const float*)d_in[9];
    const float* c2_b1  = (const float*)d_in[10];
    const float* c2_g1  = (const float*)d_in[11];
    const float* c2_be1 = (const float*)d_in[12];
    const float* c2_w2  = (const float*)d_in[13];
    const float* c2_b2  = (const float*)d_in[14];
    const float* c2_g2  = (const float*)d_in[15];
    const float* c2_be2 = (const float*)d_in[16];
    const float* cls_w1 = (const float*)d_in[17];
    const float* cls_b1 = (const float*)d_in[18];
    const float* cls_g1 = (const float*)d_in[19];
    const float* cls_be1= (const float*)d_in[20];
    const float* cls_w2 = (const float*)d_in[21];
    const float* cls_b2 = (const float*)d_in[22];
    float* out = (float*)d_out;

    int* idx_ptr;   cudaGetSymbolAddress((void**)&idx_ptr, g_idx);
    uint32_t* wimg; cudaGetSymbolAddress((void**)&wimg, g_wimg);
    float *p1, *q1, *p2, *q2, *zero, *x1;
    uint32_t *x1mx, *x1mn, *x2mx, *x2mn;
    cudaGetSymbolAddress((void**)&p1, g_P1);
    cudaGetSymbolAddress((void**)&q1, g_Q1);
    cudaGetSymbolAddress((void**)&p2, g_P2);
    cudaGetSymbolAddress((void**)&q2, g_Q2);
    cudaGetSymbolAddress((void**)&zero, g_zero);
    cudaGetSymbolAddress((void**)&x1, g_x1);
    cudaGetSymbolAddress((void**)&x1mx, g_x1mx);
    cudaGetSymbolAddress((void**)&x1mn, g_x1mn);
    cudaGetSymbolAddress((void**)&x2mx, g_x2mx);
    cudaGetSymbolAddress((void**)&x2mn, g_x2mn);

    const int SMB128 = (2*128*36 + 2*32*136) * 4;                       // 71680
    const int SMB64  = (2*128*36 + 2*32*72)  * 4;                       // 55296
    const int SMKNN  = (2*128*36 + 2*32*136 + 128*133 + 256) * 4;       // 140800
    cudaFuncSetAttribute(tgemm_kernel<64,64,3>,   cudaFuncAttributeMaxDynamicSharedMemorySize, SMB64);
    cudaFuncSetAttribute(tgemm_kernel<64,128,4>,  cudaFuncAttributeMaxDynamicSharedMemorySize, SMB128);
    cudaFuncSetAttribute(tgemm_kernel<128,128,3>, cudaFuncAttributeMaxDynamicSharedMemorySize, SMB128);
    cudaFuncSetAttribute(tgemm_kernel<192,128,2>, cudaFuncAttributeMaxDynamicSharedMemorySize, SMB128);
    cudaFuncSetAttribute(knn64_kernel,            cudaFuncAttributeMaxDynamicSharedMemorySize, SMKNN);

    // launch order: #4 (1-based) = tgemm<64,64,3> for the ncu capture (control)
    knn4_kernel<<<BB*(NN/128), 128>>>(x, idx_ptr);                                  // 1
    prep_kernel<<<14440, 256>>>(x, c1_w1, c1_b1, c1_w2, c2_w1, c2_w2, cls_w1, wimg);// 2
    stats1_kernel<64><<<R_EDGE/320, 256>>>(p1, q1, 0);                              // 3
    tgemm_kernel<64,64,3><<<R_EDGE/128, 256, SMB64>>>(1, 0, wimg + OFF_C1L2, c1_b2,
        c1_g1, c1_be1, (float)R_EDGE, p1, q1, nullptr, x1mx, x1mn,
        nullptr, nullptr, nullptr);                                                 // 4 <- ncu
    finalize_x1_kernel<<<BN_TOTAL*64/256, 256>>>(c1_g2, c1_be2);                    // 5
    knn64_kernel<<<BB*32, 256, SMKNN>>>(idx_ptr);                                   // 6
    tgemm_kernel<64,128,4><<<2*(BN_TOTAL/128), 256, SMB128>>>(-1, 0, wimg + OFF_P2, c2_b1,
        nullptr, nullptr, 0.f, x1, nullptr, p2, nullptr, nullptr,
        wimg + OFF_Q2, zero, q2);                                                   // 7
    stats1_kernel<128><<<R_EDGE/320, 256>>>(p2, q2, 2);                             // 8
    tgemm_kernel<128,128,3><<<R_EDGE/128, 256, SMB128>>>(3, 2, wimg + OFF_C2L2, c2_b2,
        c2_g1, c2_be1, (float)R_EDGE, p2, q2, nullptr, x2mx, x2mn,
        nullptr, nullptr, nullptr);                                                 // 9
    tgemm_kernel<192,128,2><<<BN_TOTAL/128, 256, SMB128>>>(4, 3, wimg + OFF_CLS, cls_b1,
        c2_g2, c2_be2, (float)R_EDGE, x1, nullptr, nullptr, x2mx, x2mn,
        nullptr, nullptr, nullptr);                                                 // 10
    cls_final_kernel<<<BN_TOTAL/8, 256>>>(cls_w2, cls_b2, cls_g1, cls_be1, out);    // 11
}